// round 16
// baseline (speedup 1.0000x reference)
#include <cuda_runtime.h>
#include <cuda_bf16.h>
#include <cstdint>

#define NN 20000
#define NE 320000
#define NG 256
#define DIM 256
#define NLAYER 4
#define EPS_BN 1e-5f
#define MTILE 160
#define NB_STAT 125   // 20000/160 = gemm grid.x (exact)

// ---------------- device scratch (static, no allocation) ----------------
__device__ __align__(16) float g_h[(size_t)NN * DIM];
__device__ __align__(16) __nv_bfloat16 g_xh[(size_t)NN * DIM];
__device__ __align__(16) __nv_bfloat16 g_xl[(size_t)NN * DIM];
__device__ __align__(16) __nv_bfloat16 g_aggh[(size_t)NN * DIM];
__device__ __align__(16) __nv_bfloat16 g_aggl[(size_t)NN * DIM];
__device__ float g_invdeg[NN];
__device__ int   g_deg[NN];
__device__ int   g_fillpos[NN];
__device__ int   g_rowptr[NN + 1];
__device__ int   g_colidx[NE];
__device__ int   g_colidx2[NE];
__device__ float g_psum[NB_STAT * DIM];
__device__ float g_psum2[NB_STAT * DIM];
__device__ float g_bn_a[DIM];
__device__ float g_bn_b[DIM];
__device__ int   g_ctr[NLAYER];
__device__ int   g_flag[NLAYER * NB_STAT];
// transposed bf16 weights: [L][256 n][512 k] (within 2x-sized legacy buffer)
__device__ __align__(16) __nv_bfloat16 g_wt[(size_t)NLAYER * 2 * 256 * 512];

__device__ __forceinline__ uint32_t smem_u32(const void* p) {
    uint32_t a;
    asm("{ .reg .u64 t; cvta.to.shared.u64 t, %1; cvt.u32.u64 %0, t; }" : "=r"(a) : "l"(p));
    return a;
}

__device__ __forceinline__ void split_pair(float x, float y, uint32_t& h, uint32_t& l) {
    __nv_bfloat162 hb = __floats2bfloat162_rn(x, y);
    float hx = __low2float(hb), hy = __high2float(hb);
    __nv_bfloat162 lb = __floats2bfloat162_rn(x - hx, y - hy);
    h = *reinterpret_cast<uint32_t*>(&hb);
    l = *reinterpret_cast<uint32_t*>(&lb);
}

// ---------------- input conversion (+ zero of counters/flags) ----------------
__global__ void cvt_x_kernel(const float* __restrict__ x) {
    int t = blockIdx.x * blockDim.x + threadIdx.x;
    if (t < NN) { g_deg[t] = 0; g_fillpos[t] = 0; }
    if (t < NLAYER) g_ctr[t] = 0;
    if (t < NLAYER * NB_STAT) g_flag[t] = 0;
    size_t e = (size_t)t * 8;
    if (e >= (size_t)NN * DIM) return;
    float4 v0 = *(const float4*)(x + e);
    float4 v1 = *(const float4*)(x + e + 4);
    uint32_t h[4], l[4];
    split_pair(v0.x, v0.y, h[0], l[0]);
    split_pair(v0.z, v0.w, h[1], l[1]);
    split_pair(v1.x, v1.y, h[2], l[2]);
    split_pair(v1.z, v1.w, h[3], l[3]);
    *(uint4*)(g_xh + e) = make_uint4(h[0], h[1], h[2], h[3]);
    *(uint4*)(g_xl + e) = make_uint4(l[0], l[1], l[2], l[3]);
}

// ---------------- graph structure build ----------------
__global__ void deg_kernel(const int* __restrict__ ei) {
    int e = blockIdx.x * blockDim.x + threadIdx.x;
    if (e >= NE) return;
    atomicAdd(&g_deg[ei[NE + e]], 1);
}

// single-block scan (smem-staged), also emits invdeg. 1024 threads.
__global__ void scan_kernel() {
    extern __shared__ int sdeg[];
    __shared__ int wsum[32];
    int tid = threadIdx.x;
    for (int i = tid; i < NN; i += 1024) {
        int d = g_deg[i];
        sdeg[i] = d;
        g_invdeg[i] = (d > 0) ? 1.0f / (float)d : 0.0f;
    }
    __syncthreads();
    const int PER = 20;  // 1024*20 = 20480 >= NN
    int i0 = tid * PER;
    int s = 0;
#pragma unroll 4
    for (int j = 0; j < PER; j++) {
        int i = i0 + j;
        if (i < NN) s += sdeg[i];
    }
    int lane = tid & 31, warp = tid >> 5;
    int inc = s;
    for (int off = 1; off < 32; off <<= 1) {
        int t = __shfl_up_sync(0xFFFFFFFFu, inc, off);
        if (lane >= off) inc += t;
    }
    if (lane == 31) wsum[warp] = inc;
    __syncthreads();
    if (warp == 0) {
        int v = wsum[lane];
        for (int off = 1; off < 32; off <<= 1) {
            int t = __shfl_up_sync(0xFFFFFFFFu, v, off);
            if (lane >= off) v += t;
        }
        wsum[lane] = v;
    }
    __syncthreads();
    int prefix = inc - s + (warp > 0 ? wsum[warp - 1] : 0);  // exclusive
    int run = prefix;
    for (int j = 0; j < PER; j++) {
        int i = i0 + j;
        if (i < NN) { int d = sdeg[i]; sdeg[i] = run; run += d; }
    }
    if (tid == 1023) g_rowptr[NN] = run;
    __syncthreads();
    for (int i = tid; i < NN; i += 1024) g_rowptr[i] = sdeg[i];
}

__global__ void fill_kernel(const int* __restrict__ ei) {
    int e = blockIdx.x * blockDim.x + threadIdx.x;
    if (e >= NE) return;
    int src = ei[e];
    int dst = ei[NE + e];
    int p = atomicAdd(&g_fillpos[dst], 1);
    g_colidx[g_rowptr[dst] + p] = src;
}

// warp-parallel stable rank sort per adjacency list (deterministic sum order)
__global__ void reorder_kernel() {
    int warp = (blockIdx.x * blockDim.x + threadIdx.x) >> 5;
    int lane = threadIdx.x & 31;
    if (warp >= NN) return;
    int b = g_rowptr[warp], e = g_rowptr[warp + 1];
    int d = e - b;
    for (int i = lane; i < d; i += 32) {
        int key = g_colidx[b + i];
        int rank = 0;
        for (int j = 0; j < d; j++) {
            int kj = g_colidx[b + j];
            rank += (kj < key) || (kj == key && j < i);
        }
        g_colidx2[b + rank] = key;
    }
}

// ---------------- weight transpose + bf16 ----------------
__global__ void wtconv_kernel(const float* __restrict__ Wl, const float* __restrict__ Wr) {
    __shared__ float t[32][33];
    int L = blockIdx.z, k0 = blockIdx.x * 32, n0 = blockIdx.y * 32;
    int tx = threadIdx.x, ty = threadIdx.y;
    const float* W = (k0 < 256) ? (Wl + (size_t)L * 65536 + (size_t)k0 * 256)
                                : (Wr + (size_t)L * 65536 + (size_t)(k0 - 256) * 256);
    t[ty][tx] = W[(size_t)ty * 256 + n0 + tx];
    __syncthreads();
    float v = t[tx][ty];  // = W[k0+tx][n0+ty]
    int n = n0 + ty, k = k0 + tx;
    __nv_bfloat16 hb = __float2bfloat16(v);
    size_t base = (size_t)L * 262144;
    g_wt[base + (size_t)n * 512 + k] = hb;
}

// ---------- FUSED per-layer kernel: gather(own 80 rows) + GEMM + BN ----------
// grid (125, 2); block (bx,by) gathers rows m0+by*80 .. +80, flags, spins for
// partner, then computes the 160x128 GEMM tile (n0 = by*128).
#define AHI 0
#define ALO 12800
#define BHI 25600
#define STAGE 35840
#define GSM (2 * STAGE)

#define CPA(dst, src, sz) \
    asm volatile("cp.async.cg.shared.global [%0], [%1], 16, %2;" \
        :: "r"(dst), "l"(src), "r"(sz) : "memory")
#define CPC() asm volatile("cp.async.commit_group;" ::: "memory")
#define CPW(n) asm volatile("cp.async.wait_group %0;" :: "n"(n) : "memory")

#define LDSM4(r, addr) \
    asm volatile("ldmatrix.sync.aligned.m8n8.x4.shared.b16 {%0,%1,%2,%3}, [%4];" \
        : "=r"((r)[0]), "=r"((r)[1]), "=r"((r)[2]), "=r"((r)[3]) : "r"(addr))

#define MMA16816(c, a, b0_, b1_) \
    asm volatile("mma.sync.aligned.m16n8k16.row.col.f32.bf16.bf16.f32 " \
        "{%0,%1,%2,%3}, {%4,%5,%6,%7}, {%8,%9}, {%0,%1,%2,%3};" \
        : "+f"((c)[0]), "+f"((c)[1]), "+f"((c)[2]), "+f"((c)[3]) \
        : "r"((a)[0]), "r"((a)[1]), "r"((a)[2]), "r"((a)[3]), "r"(b0_), "r"(b1_))

__device__ __forceinline__ void load_stage(int s, uint32_t sb, int m0,
                                           const __nv_bfloat16* wtL) {
    const __nv_bfloat16* Ah = (s < 8) ? g_aggh : g_xh;
    const __nv_bfloat16* Al = (s < 8) ? g_aggl : g_xl;
    int kg = (s & 7) * 32;
    int tid = threadIdx.x;
#pragma unroll
    for (int i = 0; i < 3; i++) {
        int idx = tid + i * 256;
        if (idx < 640) {
            int row = idx >> 2, q = idx & 3;
            size_t so = (size_t)(m0 + row) * 256 + kg + q * 8;
            uint32_t off = (uint32_t)row * 80 + q * 16;
            CPA(sb + AHI + off, Ah + so, 16u);
            CPA(sb + ALO + off, Al + so, 16u);
        }
    }
#pragma unroll
    for (int i = 0; i < 2; i++) {
        int idx = tid + i * 256;
        int row = idx >> 2, q = idx & 3;
        const __nv_bfloat16* src = wtL + (size_t)row * 512 + s * 32 + q * 8;
        uint32_t off = (uint32_t)row * 80 + q * 16;
        CPA(sb + BHI + off, src, 16u);
    }
}

__global__ void __launch_bounds__(256, 2)
layer_kernel(int layer, const float* __restrict__ xext, const float* __restrict__ bl_,
             const float* __restrict__ gamma, const float* __restrict__ beta) {
    extern __shared__ char sm[];
    __shared__ float sred[2][128][2];
    __shared__ int is_last;
    uint32_t sb = smem_u32(sm);
    int tid = threadIdx.x;
    int lane = tid & 31, wid = tid >> 5;
    int m0 = blockIdx.x * MTILE, n0 = blockIdx.y * 128;

    // ================= phase 1: gather 80 rows (warp per node) =================
    {
        const float* src = (layer > 0) ? (const float*)g_h : xext;
        int col = lane * 8;
        float bna[8], bnb[8];
        if (layer > 0) {
            float4 a0 = *(const float4*)(g_bn_a + col);
            float4 a1 = *(const float4*)(g_bn_a + col + 4);
            float4 c0 = *(const float4*)(g_bn_b + col);
            float4 c1 = *(const float4*)(g_bn_b + col + 4);
            bna[0] = a0.x; bna[1] = a0.y; bna[2] = a0.z; bna[3] = a0.w;
            bna[4] = a1.x; bna[5] = a1.y; bna[6] = a1.z; bna[7] = a1.w;
            bnb[0] = c0.x; bnb[1] = c0.y; bnb[2] = c0.z; bnb[3] = c0.w;
            bnb[4] = c1.x; bnb[5] = c1.y; bnb[6] = c1.z; bnb[7] = c1.w;
        }
        int nbase = m0 + (int)blockIdx.y * 80 + wid * 10;
        for (int j = 0; j < 10; j++) {
            int node = nbase + j;
            int b = g_rowptr[node], e = g_rowptr[node + 1];
            float acc[8] = {0, 0, 0, 0, 0, 0, 0, 0};
            for (int jj = b; jj < e; jj++) {
                int u = g_colidx2[jj];
                const float4* p = (const float4*)(src + (size_t)u * DIM + col);
                float4 v0 = p[0], v1 = p[1];
                float v[8] = {v0.x, v0.y, v0.z, v0.w, v1.x, v1.y, v1.z, v1.w};
#pragma unroll
                for (int q = 0; q < 8; q++) {
                    float t = (layer > 0) ? fmaxf(v[q] * bna[q] + bnb[q], 0.f) : v[q];
                    acc[q] += t;
                }
            }
            float s = g_invdeg[node];
            uint32_t h[4], l[4];
#pragma unroll
            for (int q = 0; q < 4; q++)
                split_pair(acc[2 * q] * s, acc[2 * q + 1] * s, h[q], l[q]);
            size_t off = (size_t)node * DIM + col;
            *(uint4*)(g_aggh + off) = make_uint4(h[0], h[1], h[2], h[3]);
            *(uint4*)(g_aggl + off) = make_uint4(l[0], l[1], l[2], l[3]);
            if (layer > 0) {
                const float4* p = (const float4*)(src + off);
                float4 v0 = p[0], v1 = p[1];
                float v[8] = {v0.x, v0.y, v0.z, v0.w, v1.x, v1.y, v1.z, v1.w};
                uint32_t hh[4], ll[4];
#pragma unroll
                for (int q = 0; q < 4; q++) {
                    float y0 = fmaxf(v[2 * q] * bna[2 * q] + bnb[2 * q], 0.f);
                    float y1 = fmaxf(v[2 * q + 1] * bna[2 * q + 1] + bnb[2 * q + 1], 0.f);
                    split_pair(y0, y1, hh[q], ll[q]);
                }
                *(uint4*)(g_xh + off) = make_uint4(hh[0], hh[1], hh[2], hh[3]);
                *(uint4*)(g_xl + off) = make_uint4(ll[0], ll[1], ll[2], ll[3]);
            }
        }
    }
    // ---- m-tile pair sync: wait for the partner block's 80 rows ----
    __syncthreads();
    if (tid == 0) {
        __threadfence();
        int* fl = &g_flag[layer * NB_STAT + blockIdx.x];
        atomicAdd(fl, 1);
        while (*(volatile int*)fl < 2) __nanosleep(64);
    }
    __syncthreads();

    // ================= phase 2: GEMM + fused BN =================
    int wm = wid >> 2, wn = wid & 3;           // warp tile: 80(M) x 32(N)
    const __nv_bfloat16* wtL = g_wt + (size_t)layer * 262144 + (size_t)n0 * 512;

    float C[5][4][4];
#pragma unroll
    for (int i = 0; i < 5; i++)
#pragma unroll
        for (int j = 0; j < 4; j++)
#pragma unroll
            for (int q = 0; q < 4; q++) C[i][j][q] = 0.0f;

    uint32_t a_row = (uint32_t)(wm * 80 + (lane & 15));
    uint32_t a_koff = (uint32_t)((lane >> 4) * 8);
    uint32_t b_row = (uint32_t)(wn * 32 + ((lane >> 4) & 1) * 8 + (lane & 7));
    uint32_t b_koff = (uint32_t)(((lane >> 3) & 1) * 8);

    load_stage(0, sb, m0, wtL);
    CPC();

    for (int s = 0; s < 16; s++) {
        if (s < 15) {
            load_stage(s + 1, sb + ((uint32_t)(s + 1) & 1u) * STAGE, m0, wtL);
            CPC();
            CPW(1);
        } else {
            CPW(0);
        }
        __syncthreads();
        uint32_t bufb = sb + ((uint32_t)s & 1u) * STAGE;
#pragma unroll
        for (int kl = 0; kl < 32; kl += 16) {
            uint32_t bh[2][4];
#pragma unroll
            for (int nf16 = 0; nf16 < 2; nf16++) {
                uint32_t ro = (b_row + nf16 * 16) * 80 + (b_koff + kl) * 2;
                LDSM4(bh[nf16], bufb + BHI + ro);
            }
#pragma unroll
            for (int mf = 0; mf < 5; mf++) {
                uint32_t ah[4], al[4];
                uint32_t ro = (a_row + mf * 16) * 80 + (a_koff + kl) * 2;
                LDSM4(ah, bufb + AHI + ro);
                LDSM4(al, bufb + ALO + ro);
#pragma unroll
                for (int nf = 0; nf < 4; nf++) {
                    uint32_t b0 = bh[nf >> 1][(nf & 1) * 2];
                    uint32_t b1 = bh[nf >> 1][(nf & 1) * 2 + 1];
                    MMA16816(C[mf][nf], ah, b0, b1);
                    MMA16816(C[mf][nf], al, b0, b1);
                }
            }
        }
        __syncthreads();
    }
    // ---- epilogue: bias + store + fused BN stats ----
    int mbase = m0 + wm * 80;
    int nbase = n0 + wn * 32;
    float ts[4][2], ts2[4][2];
#pragma unroll
    for (int nf = 0; nf < 4; nf++) {
        ts[nf][0] = ts[nf][1] = 0.f;
        ts2[nf][0] = ts2[nf][1] = 0.f;
    }
#pragma unroll
    for (int mf = 0; mf < 5; mf++) {
#pragma unroll
        for (int nf = 0; nf < 4; nf++) {
            int c = nbase + nf * 8 + (lane & 3) * 2;
            float bv0 = bl_[c], bv1 = bl_[c + 1];
            int r0 = mbase + mf * 16 + (lane >> 2);
            {
                float ox = C[mf][nf][0] + bv0, oy = C[mf][nf][1] + bv1;
                *(float2*)(g_h + (size_t)r0 * 256 + c) = make_float2(ox, oy);
                ts[nf][0] += ox; ts2[nf][0] += ox * ox;
                ts[nf][1] += oy; ts2[nf][1] += oy * oy;
            }
            {
                int r1 = r0 + 8;
                float ox = C[mf][nf][2] + bv0, oy = C[mf][nf][3] + bv1;
                *(float2*)(g_h + (size_t)r1 * 256 + c) = make_float2(ox, oy);
                ts[nf][0] += ox; ts2[nf][0] += ox * ox;
                ts[nf][1] += oy; ts2[nf][1] += oy * oy;
            }
        }
    }
#pragma unroll
    for (int nf = 0; nf < 4; nf++) {
#pragma unroll
        for (int i = 0; i < 2; i++) {
#pragma unroll
            for (int msk = 4; msk < 32; msk <<= 1) {
                ts[nf][i] += __shfl_xor_sync(0xFFFFFFFFu, ts[nf][i], msk);
                ts2[nf][i] += __shfl_xor_sync(0xFFFFFFFFu, ts2[nf][i], msk);
            }
        }
    }
    if (lane < 4) {
#pragma unroll
        for (int nf = 0; nf < 4; nf++) {
            int coll = wn * 32 + nf * 8 + lane * 2;
            sred[wm][coll][0] = ts[nf][0];
            sred[wm][coll][1] = ts2[nf][0];
            sred[wm][coll + 1][0] = ts[nf][1];
            sred[wm][coll + 1][1] = ts2[nf][1];
        }
    }
    __syncthreads();
    if (tid < 128) {
        float s = sred[0][tid][0] + sred[1][tid][0];
        float s2 = sred[0][tid][1] + sred[1][tid][1];
        int cg = blockIdx.x * 256 + n0 + tid;
        g_psum[cg] = s;
        g_psum2[cg] = s2;
    }
    // ---- fused bn_reduce: last block computes bn_a/bn_b ----
    __threadfence();
    __syncthreads();
    if (tid == 0) is_last = (atomicAdd(&g_ctr[layer], 1) == 2 * NB_STAT - 1);
    __syncthreads();
    if (is_last) {
        int d = tid;  // 0..255
        float s = 0, s2 = 0;
        for (int b = 0; b < NB_STAT; b++) {
            s += __ldcg(&g_psum[b * DIM + d]);
            s2 += __ldcg(&g_psum2[b * DIM + d]);
        }
        float mu = s / (float)NN;
        float var = s2 / (float)NN - mu * mu;
        float r = rsqrtf(var + EPS_BN);
        float a = gamma[d] * r;
        g_bn_a[d] = a;
        g_bn_b[d] = beta[d] - mu * a;
    }
}

// ---------------- fused tail: pool(bn+relu of h) + 3-layer MLP ---------------
__device__ __forceinline__ int lower_bound_batch(const int* __restrict__ batch, int g) {
    int lo = 0, hi = NN;
    while (lo < hi) {
        int mid = (lo + hi) >> 1;
        if (batch[mid] < g) lo = mid + 1; else hi = mid;
    }
    return lo;
}

__global__ void tail_kernel(const int* __restrict__ batch,
                            const float* __restrict__ fc1_w, const float* __restrict__ fc1_b,
                            const float* __restrict__ fc2_w, const float* __restrict__ fc2_b,
                            const float* __restrict__ fc3_w, const float* __restrict__ fc3_b,
                            float* __restrict__ out) {
    __shared__ float xr[256];
    __shared__ float y1[128];
    __shared__ float y2[64];
    int g = blockIdx.x;
    int n = threadIdx.x;  // 256 threads
    int r0 = lower_bound_batch(batch, g);
    int r1 = lower_bound_batch(batch, g + 1);
    float ba = g_bn_a[n], bb = g_bn_b[n];
    float s = 0;
#pragma unroll 4
    for (int r = r0; r < r1; r++) {
        float v = g_h[(size_t)r * DIM + n];
        s += fmaxf(v * ba + bb, 0.f);
    }
    int c = r1 - r0;
    xr[n] = s / (float)(c > 0 ? c : 1);
    __syncthreads();
    if (n < 128) {
        float t = fc1_b[n];
#pragma unroll 8
        for (int k = 0; k < 256; k++) t += xr[k] * fc1_w[k * 128 + n];
        y1[n] = fmaxf(t, 0.0f);
    }
    __syncthreads();
    if (n < 64) {
        float t = fc2_b[n];
#pragma unroll 8
        for (int k = 0; k < 128; k++) t += y1[k] * fc2_w[k * 64 + n];
        y2[n] = fmaxf(t, 0.0f);
    }
    __syncthreads();
    if (n < 10) {
        float t = fc3_b[n];
#pragma unroll 8
        for (int k = 0; k < 64; k++) t += y2[k] * fc3_w[k * 10 + n];
        out[g * 10 + n] = t;
    }
}

// ---------------- host launch ----------------
extern "C" void kernel_launch(void* const* d_in, const int* in_sizes, int n_in,
                              void* d_out, int out_size) {
    const float* x     = (const float*)d_in[0];
    const int*   ei    = (const int*)d_in[1];
    const int*   batch = (const int*)d_in[2];
    const float* Wl    = (const float*)d_in[3];
    const float* bl    = (const float*)d_in[4];
    const float* Wr    = (const float*)d_in[5];
    const float* gamma = (const float*)d_in[6];
    const float* beta  = (const float*)d_in[7];
    const float* fc1_w = (const float*)d_in[8];
    const float* fc1_b = (const float*)d_in[9];
    const float* fc2_w = (const float*)d_in[10];
    const float* fc2_b = (const float*)d_in[11];
    const float* fc3_w = (const float*)d_in[12];
    const float* fc3_b = (const float*)d_in[13];
    float* out = (float*)d_out;

    static bool attr_set = false;
    if (!attr_set) {
        cudaFuncSetAttribute(layer_kernel, cudaFuncAttributeMaxDynamicSharedMemorySize, GSM);
        cudaFuncSetAttribute(scan_kernel, cudaFuncAttributeMaxDynamicSharedMemorySize, NN * 4);
        attr_set = true;
    }

    // structure + conversions
    cvt_x_kernel<<<(NN * DIM / 8 + 255) / 256, 256>>>(x);   // also zeroes counters/flags
    deg_kernel<<<(NE + 255) / 256, 256>>>(ei);
    scan_kernel<<<1, 1024, NN * 4>>>();
    fill_kernel<<<(NE + 255) / 256, 256>>>(ei);
    reorder_kernel<<<(NN * 32 + 255) / 256, 256>>>();
    wtconv_kernel<<<dim3(16, 8, NLAYER), dim3(32, 32)>>>(Wl, Wr);

    for (int i = 0; i < NLAYER; i++) {
        layer_kernel<<<dim3(NB_STAT, 2), 256, GSM>>>(
            i, x, bl + (size_t)i * DIM, gamma + (size_t)i * DIM, beta + (size_t)i * DIM);
    }

    tail_kernel<<<NG, 256>>>(batch, fc1_w, fc1_b, fc2_w, fc2_b, fc3_w, fc3_b, out);
}

// round 17
// speedup vs baseline: 1.0849x; 1.0849x over previous
#include <cuda_runtime.h>
#include <cuda_bf16.h>
#include <cstdint>

#define NN 20000
#define NE 320000
#define NG 256
#define DIM 256
#define NLAYER 4
#define EPS_BN 1e-5f
#define MTILE 160
#define NB_STAT 125   // 20000/160 = gemm grid.x (exact)
#define SCAN_BLK 20   // 20 x 1000 = 20000

// ---------------- device scratch (static, no allocation) ----------------
__device__ __align__(16) float g_h[(size_t)NN * DIM];
__device__ __align__(16) __nv_bfloat16 g_xh[(size_t)NN * DIM];
__device__ __align__(16) __nv_bfloat16 g_xl[(size_t)NN * DIM];
__device__ __align__(16) __nv_bfloat16 g_aggh[(size_t)NN * DIM];
__device__ __align__(16) __nv_bfloat16 g_aggl[(size_t)NN * DIM];
__device__ float g_invdeg[NN];
__device__ int   g_deg[NN];
__device__ int   g_fillpos[NN];
__device__ int   g_rowptr[NN + 1];
__device__ int   g_colidx[NE];
__device__ int   g_colidx2[NE];
__device__ int   g_bsum[SCAN_BLK];
__device__ float g_psum[NB_STAT * DIM];
__device__ float g_psum2[NB_STAT * DIM];
__device__ float g_bn_a[DIM];
__device__ float g_bn_b[DIM];
__device__ int   g_ctr[NLAYER];
// transposed bf16 weights: [L][256 n][512 k] (2x-sized legacy buffer)
__device__ __align__(16) __nv_bfloat16 g_wt[(size_t)NLAYER * 2 * 256 * 512];

__device__ __forceinline__ uint32_t smem_u32(const void* p) {
    uint32_t a;
    asm("{ .reg .u64 t; cvta.to.shared.u64 t, %1; cvt.u32.u64 %0, t; }" : "=r"(a) : "l"(p));
    return a;
}

__device__ __forceinline__ void split_pair(float x, float y, uint32_t& h, uint32_t& l) {
    __nv_bfloat162 hb = __floats2bfloat162_rn(x, y);
    float hx = __low2float(hb), hy = __high2float(hb);
    __nv_bfloat162 lb = __floats2bfloat162_rn(x - hx, y - hy);
    h = *reinterpret_cast<uint32_t*>(&hb);
    l = *reinterpret_cast<uint32_t*>(&lb);
}

// ---------------- input conversion (+ zero of counters) ----------------
__global__ void cvt_x_kernel(const float* __restrict__ x) {
    int t = blockIdx.x * blockDim.x + threadIdx.x;
    if (t < NN) { g_deg[t] = 0; g_fillpos[t] = 0; }
    if (t < NLAYER) g_ctr[t] = 0;
    size_t e = (size_t)t * 8;
    if (e >= (size_t)NN * DIM) return;
    float4 v0 = *(const float4*)(x + e);
    float4 v1 = *(const float4*)(x + e + 4);
    uint32_t h[4], l[4];
    split_pair(v0.x, v0.y, h[0], l[0]);
    split_pair(v0.z, v0.w, h[1], l[1]);
    split_pair(v1.x, v1.y, h[2], l[2]);
    split_pair(v1.z, v1.w, h[3], l[3]);
    *(uint4*)(g_xh + e) = make_uint4(h[0], h[1], h[2], h[3]);
    *(uint4*)(g_xl + e) = make_uint4(l[0], l[1], l[2], l[3]);
}

// ---------------- graph structure build ----------------
__global__ void deg_kernel(const int* __restrict__ ei) {
    int e = blockIdx.x * blockDim.x + threadIdx.x;
    if (e >= NE) return;
    atomicAdd(&g_deg[ei[NE + e]], 1);
}

// phase-1 scan: 20 blocks x 1000 elems; local exclusive scan + block sums
__global__ void scan1_kernel() {
    __shared__ int wsum[32];
    int b = blockIdx.x, tid = threadIdx.x;
    int i = b * 1000 + tid;
    int v = 0;
    if (tid < 1000) {
        v = g_deg[i];
        g_invdeg[i] = (v > 0) ? 1.0f / (float)v : 0.0f;
    }
    int lane = tid & 31, warp = tid >> 5;
    int inc = v;
    for (int off = 1; off < 32; off <<= 1) {
        int t = __shfl_up_sync(0xFFFFFFFFu, inc, off);
        if (lane >= off) inc += t;
    }
    if (lane == 31) wsum[warp] = inc;
    __syncthreads();
    if (warp == 0) {
        int w = wsum[lane];
        for (int off = 1; off < 32; off <<= 1) {
            int t = __shfl_up_sync(0xFFFFFFFFu, w, off);
            if (lane >= off) w += t;
        }
        wsum[lane] = w;
    }
    __syncthreads();
    int prefix = inc - v + (warp > 0 ? wsum[warp - 1] : 0);
    if (tid < 1000) g_rowptr[i] = prefix;
    if (tid == 0) g_bsum[b] = wsum[31];
}

// phase-2: add scanned block offsets
__global__ void scan2_kernel() {
    __shared__ int off_sh;
    int b = blockIdx.x, tid = threadIdx.x;
    if (tid == 0) {
        int o = 0;
        for (int j = 0; j < b; j++) o += g_bsum[j];
        off_sh = o;
        if (b == SCAN_BLK - 1) g_rowptr[NN] = o + g_bsum[b];
    }
    __syncthreads();
    int i = b * 1000 + tid;
    if (tid < 1000) g_rowptr[i] += off_sh;
}

__global__ void fill_kernel(const int* __restrict__ ei) {
    int e = blockIdx.x * blockDim.x + threadIdx.x;
    if (e >= NE) return;
    int src = ei[e];
    int dst = ei[NE + e];
    int p = atomicAdd(&g_fillpos[dst], 1);
    g_colidx[g_rowptr[dst] + p] = src;
}

// warp-parallel stable rank sort per adjacency list (deterministic sum order)
__global__ void reorder_kernel() {
    int warp = (blockIdx.x * blockDim.x + threadIdx.x) >> 5;
    int lane = threadIdx.x & 31;
    if (warp >= NN) return;
    int b = g_rowptr[warp], e = g_rowptr[warp + 1];
    int d = e - b;
    for (int i = lane; i < d; i += 32) {
        int key = g_colidx[b + i];
        int rank = 0;
        for (int j = 0; j < d; j++) {
            int kj = g_colidx[b + j];
            rank += (kj < key) || (kj == key && j < i);
        }
        g_colidx2[b + rank] = key;
    }
}

// ---------------- weight transpose + bf16 ----------------
__global__ void wtconv_kernel(const float* __restrict__ Wl, const float* __restrict__ Wr) {
    __shared__ float t[32][33];
    int L = blockIdx.z, k0 = blockIdx.x * 32, n0 = blockIdx.y * 32;
    int tx = threadIdx.x, ty = threadIdx.y;
    const float* W = (k0 < 256) ? (Wl + (size_t)L * 65536 + (size_t)k0 * 256)
                                : (Wr + (size_t)L * 65536 + (size_t)(k0 - 256) * 256);
    t[ty][tx] = W[(size_t)ty * 256 + n0 + tx];
    __syncthreads();
    float v = t[tx][ty];  // = W[k0+tx][n0+ty]
    int n = n0 + ty, k = k0 + tx;
    __nv_bfloat16 hb = __float2bfloat16(v);
    size_t base = (size_t)L * 262144;
    g_wt[base + (size_t)n * 512 + k] = hb;
}

// -------- mean aggregation (warp per node) fused with BN+ReLU+split ---------
template <bool USE_BN>
__global__ void gather_kernel(const float* __restrict__ xext) {
    int warp = (blockIdx.x * blockDim.x + threadIdx.x) >> 5;
    int lane = threadIdx.x & 31;
    if (warp >= NN) return;
    const float* src = USE_BN ? (const float*)g_h : xext;
    int b = g_rowptr[warp], e = g_rowptr[warp + 1];
    int col = lane * 8;
    float bna[8], bnb[8];
    if (USE_BN) {
        float4 a0 = *(const float4*)(g_bn_a + col);
        float4 a1 = *(const float4*)(g_bn_a + col + 4);
        float4 c0 = *(const float4*)(g_bn_b + col);
        float4 c1 = *(const float4*)(g_bn_b + col + 4);
        bna[0] = a0.x; bna[1] = a0.y; bna[2] = a0.z; bna[3] = a0.w;
        bna[4] = a1.x; bna[5] = a1.y; bna[6] = a1.z; bna[7] = a1.w;
        bnb[0] = c0.x; bnb[1] = c0.y; bnb[2] = c0.z; bnb[3] = c0.w;
        bnb[4] = c1.x; bnb[5] = c1.y; bnb[6] = c1.z; bnb[7] = c1.w;
    }
    float acc[8] = {0, 0, 0, 0, 0, 0, 0, 0};
    for (int j = b; j < e; j++) {
        int u = g_colidx2[j];
        const float4* p = (const float4*)(src + (size_t)u * DIM + col);
        float4 v0 = p[0], v1 = p[1];
        float v[8] = {v0.x, v0.y, v0.z, v0.w, v1.x, v1.y, v1.z, v1.w};
#pragma unroll
        for (int q = 0; q < 8; q++) {
            float t = USE_BN ? fmaxf(v[q] * bna[q] + bnb[q], 0.f) : v[q];
            acc[q] += t;
        }
    }
    float s = g_invdeg[warp];
    uint32_t h[4], l[4];
#pragma unroll
    for (int q = 0; q < 4; q++) split_pair(acc[2 * q] * s, acc[2 * q + 1] * s, h[q], l[q]);
    size_t off = (size_t)warp * DIM + col;
    *(uint4*)(g_aggh + off) = make_uint4(h[0], h[1], h[2], h[3]);
    *(uint4*)(g_aggl + off) = make_uint4(l[0], l[1], l[2], l[3]);
    if (USE_BN) {
        const float4* p = (const float4*)(src + off);
        float4 v0 = p[0], v1 = p[1];
        float v[8] = {v0.x, v0.y, v0.z, v0.w, v1.x, v1.y, v1.z, v1.w};
        uint32_t hh[4], ll[4];
#pragma unroll
        for (int q = 0; q < 4; q++) {
            float y0 = fmaxf(v[2 * q] * bna[2 * q] + bnb[2 * q], 0.f);
            float y1 = fmaxf(v[2 * q + 1] * bna[2 * q + 1] + bnb[2 * q + 1], 0.f);
            split_pair(y0, y1, hh[q], ll[q]);
        }
        *(uint4*)(g_xh + off) = make_uint4(hh[0], hh[1], hh[2], hh[3]);
        *(uint4*)(g_xl + off) = make_uint4(ll[0], ll[1], ll[2], ll[3]);
    }
}

// ---------- pipelined mma.sync GEMM + fused BN stats + fused bn_reduce -------
// block 160(M) x 128(N), 8 warps each 80x32, K=512 in 16 stages of 32.
// per stage (35840 B): Ahi@0 (stride 80B), Alo@12800, Bhi@25600. 3-stage pipeline.
#define AHI 0
#define ALO 12800
#define BHI 25600
#define STAGE 35840
#define GSM (3 * STAGE)

#define CPA(dst, src, sz) \
    asm volatile("cp.async.cg.shared.global [%0], [%1], 16, %2;" \
        :: "r"(dst), "l"(src), "r"(sz) : "memory")
#define CPC() asm volatile("cp.async.commit_group;" ::: "memory")
#define CPW(n) asm volatile("cp.async.wait_group %0;" :: "n"(n) : "memory")

#define LDSM4(r, addr) \
    asm volatile("ldmatrix.sync.aligned.m8n8.x4.shared.b16 {%0,%1,%2,%3}, [%4];" \
        : "=r"((r)[0]), "=r"((r)[1]), "=r"((r)[2]), "=r"((r)[3]) : "r"(addr))

#define MMA16816(c, a, b0_, b1_) \
    asm volatile("mma.sync.aligned.m16n8k16.row.col.f32.bf16.bf16.f32 " \
        "{%0,%1,%2,%3}, {%4,%5,%6,%7}, {%8,%9}, {%0,%1,%2,%3};" \
        : "+f"((c)[0]), "+f"((c)[1]), "+f"((c)[2]), "+f"((c)[3]) \
        : "r"((a)[0]), "r"((a)[1]), "r"((a)[2]), "r"((a)[3]), "r"(b0_), "r"(b1_))

__device__ __forceinline__ void load_stage(int s, uint32_t sb, int m0,
                                           const __nv_bfloat16* wtL) {
    const __nv_bfloat16* Ah = (s < 8) ? g_aggh : g_xh;
    const __nv_bfloat16* Al = (s < 8) ? g_aggl : g_xl;
    int kg = (s & 7) * 32;
    int tid = threadIdx.x;
#pragma unroll
    for (int i = 0; i < 3; i++) {
        int idx = tid + i * 256;
        if (idx < 640) {
            int row = idx >> 2, q = idx & 3;
            size_t so = (size_t)(m0 + row) * 256 + kg + q * 8;
            uint32_t off = (uint32_t)row * 80 + q * 16;
            CPA(sb + AHI + off, Ah + so, 16u);
            CPA(sb + ALO + off, Al + so, 16u);
        }
    }
#pragma unroll
    for (int i = 0; i < 2; i++) {
        int idx = tid + i * 256;
        int row = idx >> 2, q = idx & 3;
        const __nv_bfloat16* src = wtL + (size_t)row * 512 + s * 32 + q * 8;
        uint32_t off = (uint32_t)row * 80 + q * 16;
        CPA(sb + BHI + off, src, 16u);
    }
}

__global__ void __launch_bounds__(256, 2)
gemm_mma_kernel(int layer, const float* __restrict__ bl_,
                const float* __restrict__ gamma, const float* __restrict__ beta) {
    extern __shared__ char sm[];
    __shared__ float sred[2][128][2];  // [wm][local col][{sum, sumsq}]
    __shared__ int is_last;
    uint32_t sb = smem_u32(sm);
    int tid = threadIdx.x;
    int lane = tid & 31, wid = tid >> 5;
    int wm = wid >> 2, wn = wid & 3;           // warp tile: 80(M) x 32(N)
    int m0 = blockIdx.x * MTILE, n0 = blockIdx.y * 128;
    const __nv_bfloat16* wtL = g_wt + (size_t)layer * 262144 + (size_t)n0 * 512;

    float C[5][4][4];
#pragma unroll
    for (int i = 0; i < 5; i++)
#pragma unroll
        for (int j = 0; j < 4; j++)
#pragma unroll
            for (int q = 0; q < 4; q++) C[i][j][q] = 0.0f;

    uint32_t a_row = (uint32_t)(wm * 80 + (lane & 15));
    uint32_t a_koff = (uint32_t)((lane >> 4) * 8);
    uint32_t b_row = (uint32_t)(wn * 32 + ((lane >> 4) & 1) * 8 + (lane & 7));
    uint32_t b_koff = (uint32_t)(((lane >> 3) & 1) * 8);

    load_stage(0, sb, m0, wtL);
    CPC();
    load_stage(1, sb + STAGE, m0, wtL);
    CPC();

    for (int s = 0; s < 16; s++) {
        if (s <= 13) {
            load_stage(s + 2, sb + (uint32_t)((s + 2) % 3) * STAGE, m0, wtL);
            CPC();
            CPW(2);
        } else if (s == 14) {
            CPW(1);
        } else {
            CPW(0);
        }
        __syncthreads();
        uint32_t bufb = sb + (uint32_t)(s % 3) * STAGE;
#pragma unroll
        for (int kl = 0; kl < 32; kl += 16) {
            uint32_t bh[2][4];
#pragma unroll
            for (int nf16 = 0; nf16 < 2; nf16++) {
                uint32_t ro = (b_row + nf16 * 16) * 80 + (b_koff + kl) * 2;
                LDSM4(bh[nf16], bufb + BHI + ro);
            }
#pragma unroll
            for (int mf = 0; mf < 5; mf++) {
                uint32_t ah[4], al[4];
                uint32_t ro = (a_row + mf * 16) * 80 + (a_koff + kl) * 2;
                LDSM4(ah, bufb + AHI + ro);
                LDSM4(al, bufb + ALO + ro);
#pragma unroll
                for (int nf = 0; nf < 4; nf++) {
                    uint32_t b0 = bh[nf >> 1][(nf & 1) * 2];
                    uint32_t b1 = bh[nf >> 1][(nf & 1) * 2 + 1];
                    MMA16816(C[mf][nf], ah, b0, b1);
                    MMA16816(C[mf][nf], al, b0, b1);
                }
            }
        }
        __syncthreads();
    }
    // ---- epilogue: bias + store + fused BN stats ----
    int mbase = m0 + wm * 80;
    int nbase = n0 + wn * 32;
    float ts[4][2], ts2[4][2];
#pragma unroll
    for (int nf = 0; nf < 4; nf++) {
        ts[nf][0] = ts[nf][1] = 0.f;
        ts2[nf][0] = ts2[nf][1] = 0.f;
    }
#pragma unroll
    for (int mf = 0; mf < 5; mf++) {
#pragma unroll
        for (int nf = 0; nf < 4; nf++) {
            int c = nbase + nf * 8 + (lane & 3) * 2;
            float bv0 = bl_[c], bv1 = bl_[c + 1];
            int r0 = mbase + mf * 16 + (lane >> 2);
            {
                float ox = C[mf][nf][0] + bv0, oy = C[mf][nf][1] + bv1;
                *(float2*)(g_h + (size_t)r0 * 256 + c) = make_float2(ox, oy);
                ts[nf][0] += ox; ts2[nf][0] += ox * ox;
                ts[nf][1] += oy; ts2[nf][1] += oy * oy;
            }
            {
                int r1 = r0 + 8;
                float ox = C[mf][nf][2] + bv0, oy = C[mf][nf][3] + bv1;
                *(float2*)(g_h + (size_t)r1 * 256 + c) = make_float2(ox, oy);
                ts[nf][0] += ox; ts2[nf][0] += ox * ox;
                ts[nf][1] += oy; ts2[nf][1] += oy * oy;
            }
        }
    }
#pragma unroll
    for (int nf = 0; nf < 4; nf++) {
#pragma unroll
        for (int i = 0; i < 2; i++) {
#pragma unroll
            for (int msk = 4; msk < 32; msk <<= 1) {
                ts[nf][i] += __shfl_xor_sync(0xFFFFFFFFu, ts[nf][i], msk);
                ts2[nf][i] += __shfl_xor_sync(0xFFFFFFFFu, ts2[nf][i], msk);
            }
        }
    }
    if (lane < 4) {
#pragma unroll
        for (int nf = 0; nf < 4; nf++) {
            int coll = wn * 32 + nf * 8 + lane * 2;
            sred[wm][coll][0] = ts[nf][0];
            sred[wm][coll][1] = ts2[nf][0];
            sred[wm][coll + 1][0] = ts[nf][1];
            sred[wm][coll + 1][1] = ts2[nf][1];
        }
    }
    __syncthreads();
    if (tid < 128) {
        float s = sred[0][tid][0] + sred[1][tid][0];
        float s2 = sred[0][tid][1] + sred[1][tid][1];
        int cg = blockIdx.x * 256 + n0 + tid;
        g_psum[cg] = s;
        g_psum2[cg] = s2;
    }
    // ---- fused bn_reduce: last block computes bn_a/bn_b ----
    __threadfence();
    __syncthreads();
    if (tid == 0) is_last = (atomicAdd(&g_ctr[layer], 1) == 2 * NB_STAT - 1);
    __syncthreads();
    if (is_last) {
        int d = tid;  // 0..255
        float s = 0, s2 = 0;
        for (int b = 0; b < NB_STAT; b++) {
            s += __ldcg(&g_psum[b * DIM + d]);
            s2 += __ldcg(&g_psum2[b * DIM + d]);
        }
        float mu = s / (float)NN;
        float var = s2 / (float)NN - mu * mu;
        float r = rsqrtf(var + EPS_BN);
        float a = gamma[d] * r;
        g_bn_a[d] = a;
        g_bn_b[d] = beta[d] - mu * a;
    }
}

// ---------------- fused tail: pool(bn+relu of h) + 3-layer MLP ---------------
__device__ __forceinline__ int lower_bound_batch(const int* __restrict__ batch, int g) {
    int lo = 0, hi = NN;
    while (lo < hi) {
        int mid = (lo + hi) >> 1;
        if (batch[mid] < g) lo = mid + 1; else hi = mid;
    }
    return lo;
}

__global__ void tail_kernel(const int* __restrict__ batch,
                            const float* __restrict__ fc1_w, const float* __restrict__ fc1_b,
                            const float* __restrict__ fc2_w, const float* __restrict__ fc2_b,
                            const float* __restrict__ fc3_w, const float* __restrict__ fc3_b,
                            float* __restrict__ out) {
    __shared__ float xr[256];
    __shared__ float y1[128];
    __shared__ float y2[64];
    int g = blockIdx.x;
    int n = threadIdx.x;  // 256 threads
    int r0 = lower_bound_batch(batch, g);
    int r1 = lower_bound_batch(batch, g + 1);
    float ba = g_bn_a[n], bb = g_bn_b[n];
    float s = 0;
#pragma unroll 4
    for (int r = r0; r < r1; r++) {
        float v = g_h[(size_t)r * DIM + n];
        s += fmaxf(v * ba + bb, 0.f);
    }
    int c = r1 - r0;
    xr[n] = s / (float)(c > 0 ? c : 1);
    __syncthreads();
    if (n < 128) {
        float t = fc1_b[n];
#pragma unroll 8
        for (int k = 0; k < 256; k++) t += xr[k] * fc1_w[k * 128 + n];
        y1[n] = fmaxf(t, 0.0f);
    }
    __syncthreads();
    if (n < 64) {
        float t = fc2_b[n];
#pragma unroll 8
        for (int k = 0; k < 128; k++) t += y1[k] * fc2_w[k * 64 + n];
        y2[n] = fmaxf(t, 0.0f);
    }
    __syncthreads();
    if (n < 10) {
        float t = fc3_b[n];
#pragma unroll 8
        for (int k = 0; k < 64; k++) t += y2[k] * fc3_w[k * 10 + n];
        out[g * 10 + n] = t;
    }
}

// ---------------- host launch ----------------
extern "C" void kernel_launch(void* const* d_in, const int* in_sizes, int n_in,
                              void* d_out, int out_size) {
    const float* x     = (const float*)d_in[0];
    const int*   ei    = (const int*)d_in[1];
    const int*   batch = (const int*)d_in[2];
    const float* Wl    = (const float*)d_in[3];
    const float* bl    = (const float*)d_in[4];
    const float* Wr    = (const float*)d_in[5];
    const float* gamma = (const float*)d_in[6];
    const float* beta  = (const float*)d_in[7];
    const float* fc1_w = (const float*)d_in[8];
    const float* fc1_b = (const float*)d_in[9];
    const float* fc2_w = (const float*)d_in[10];
    const float* fc2_b = (const float*)d_in[11];
    const float* fc3_w = (const float*)d_in[12];
    const float* fc3_b = (const float*)d_in[13];
    float* out = (float*)d_out;

    static bool attr_set = false;
    if (!attr_set) {
        cudaFuncSetAttribute(gemm_mma_kernel, cudaFuncAttributeMaxDynamicSharedMemorySize, GSM);
        attr_set = true;
    }

    // structure + conversions
    cvt_x_kernel<<<(NN * DIM / 8 + 255) / 256, 256>>>(x);   // also zeroes counters
    deg_kernel<<<(NE + 255) / 256, 256>>>(ei);
    scan1_kernel<<<SCAN_BLK, 1024>>>();
    scan2_kernel<<<SCAN_BLK, 1024>>>();
    fill_kernel<<<(NE + 255) / 256, 256>>>(ei);
    reorder_kernel<<<(NN * 32 + 255) / 256, 256>>>();
    wtconv_kernel<<<dim3(16, 8, NLAYER), dim3(32, 32)>>>(Wl, Wr);

    for (int i = 0; i < NLAYER; i++) {
        if (i == 0)
            gather_kernel<false><<<(NN * 32 + 255) / 256, 256>>>(x);
        else
            gather_kernel<true><<<(NN * 32 + 255) / 256, 256>>>(nullptr);
        gemm_mma_kernel<<<dim3(NB_STAT, 2), 256, GSM>>>(
            i, bl + (size_t)i * DIM, gamma + (size_t)i * DIM, beta + (size_t)i * DIM);
    }

    tail_kernel<<<NG, 256>>>(batch, fc1_w, fc1_b, fc2_w, fc2_b, fc3_w, fc3_b, out);
}